// round 11
// baseline (speedup 1.0000x reference)
#include <cuda_runtime.h>
#include <math.h>

#define Nn 512
#define Bb 8
#define Cc 64
#define Hh 64
#define Tt 16
#define Ll 2
#define Ee 16384
#define NB (Nn*Bb)          /* 4096 rows for gate GEMMs */
#define MAT (NB*Hh)         /* 262144 floats per [N,B,H] matrix */
#define NCTAS 128
#define NTHREADS 512

typedef unsigned long long u64;

// ---------------- device scratch ----------------
__device__ float g_S[Nn*Nn];
__device__ float g_S2[Nn*Nn];
__device__ float g_deg[Nn];
__device__ float g_dinv[Nn];
__device__ float g_U[(long)Tt*3*MAT];
__device__ float g_Xc[(long)Tt*Ll*3*MAT];
__device__ float g_h[MAT];
__device__ float g_z[MAT];
__device__ float g_hr[MAT];
__device__ float g_T1[MAT];
__device__ float g_T2[MAT];
__device__ float g_sp[MAT];
__device__ float g_tp[MAT];
__device__ int   g_idx32;
__device__ unsigned g_barCount = 0;   // returns to 0 after each barrier
__device__ unsigned g_barPhase = 0;   // monotonic across launches (wrap-safe)

// ---------------- f32x2 helpers ----------------
__device__ __forceinline__ u64 ffma2(u64 a, u64 b, u64 c) {
    u64 d;
    asm("fma.rn.f32x2 %0, %1, %2, %3;" : "=l"(d) : "l"(a), "l"(b), "l"(c));
    return d;
}
__device__ __forceinline__ u64 splat2(float x) {
    u64 r;
    asm("mov.b64 %0, {%1, %1};" : "=l"(r) : "r"(__float_as_uint(x)));
    return r;
}
__device__ __forceinline__ float2 u2f(u64 v) {
    float2 f;
    asm("mov.b64 {%0, %1}, %2;" : "=f"(f.x), "=f"(f.y) : "l"(v));
    return f;
}

// ---------------- grid barrier (persistent kernel, replay-proof) ----------------
__device__ __forceinline__ unsigned ld_acq(unsigned* p) {
    unsigned v;
    asm volatile("ld.acquire.gpu.u32 %0, [%1];" : "=r"(v) : "l"(p) : "memory");
    return v;
}
__device__ __forceinline__ void st_rel(unsigned* p, unsigned v) {
    asm volatile("st.release.gpu.u32 [%0], %1;" :: "l"(p), "r"(v) : "memory");
}
__device__ __forceinline__ unsigned atom_add_acqrel(unsigned* p, unsigned v) {
    unsigned old;
    asm volatile("atom.acq_rel.gpu.add.u32 %0, [%1], %2;" : "=r"(old) : "l"(p), "r"(v) : "memory");
    return old;
}
__device__ __forceinline__ void grid_bar(unsigned& bph) {
    __syncthreads();
    bph += 1;
    if (threadIdx.x == 0) {
        unsigned old = atom_add_acqrel(&g_barCount, 1u);
        if (old == NCTAS - 1) {
            g_barCount = 0;
            st_rel(&g_barPhase, bph);
        } else {
            while ((int)(ld_acq(&g_barPhase) - bph) < 0) { __nanosleep(32); }
        }
    }
    __syncthreads();
}

// ---------------- shared memory ----------------
struct SmemG {
    __align__(16) u64   As2[2][32][66];  // [buf][k][m] splatted {a,a}, 64 m (+2 pad)
    __align__(16) float Bs[2][32][64];   // [buf][k][n]
};
struct SmemP {
    float sps[64][65];
    float tps[32][65];
    float w2[64];
};
#define SMEM_BYTES (sizeof(SmemG) > sizeof(SmemP) ? sizeof(SmemG) : sizeof(SmemP))

__device__ __forceinline__ int load_idx(const void* ei, long i) {
    if (g_idx32) return ((const int*)ei)[i];
    return (int)(((const long long*)ei)[i]);
}

// ============ K=512 GEMM core: O = alpha * M @ X + beta * Y, tile 64x64, 512 thr ============
// Plain (coherent) loads only — operands are produced by other CTAs within this
// same launch; only coherent loads observe the grid_bar acquire.
__device__ __forceinline__ void gemm512_core(
        SmemG& s, const float* M, const float* X,
        const float* Y, float* O,
        float alpha, float beta, int mBase, int nBase) {
    int tid = threadIdx.x;
    int tx = tid & 15, ty = tid >> 4;   // tx: 4 cols; ty 0..31: 2 rows
    int lm  = tid >> 3;                 // 0..63  A row
    int lk4 = (tid & 7) << 2;           // A k group
    int bk  = tid >> 4;                 // 0..31  B k row
    int bn4 = (tid & 15) << 2;          // B n group

    float4 a_reg, b_reg;

    a_reg = *(const float4*)&M[(long)(mBase + lm) * 512 + lk4];
    b_reg = *(const float4*)&X[(long)bk * 512 + nBase + bn4];
    s.As2[0][lk4+0][lm] = splat2(a_reg.x); s.As2[0][lk4+1][lm] = splat2(a_reg.y);
    s.As2[0][lk4+2][lm] = splat2(a_reg.z); s.As2[0][lk4+3][lm] = splat2(a_reg.w);
    *(float4*)&s.Bs[0][bk][bn4] = b_reg;
    __syncthreads();

    u64 acc[2][2] = {{0ull, 0ull}, {0ull, 0ull}};

    for (int t = 0; t < 16; t++) {
        int cur = t & 1, nxt = cur ^ 1;
        if (t < 15) {
            int kk = (t + 1) * 32;
            a_reg = *(const float4*)&M[(long)(mBase + lm) * 512 + kk + lk4];
            b_reg = *(const float4*)&X[(long)(kk + bk) * 512 + nBase + bn4];
        }
        #pragma unroll
        for (int k = 0; k < 32; k++) {
            ulonglong2 a2 = *(const ulonglong2*)&s.As2[cur][k][ty * 2];
            ulonglong2 b2 = *(const ulonglong2*)&s.Bs[cur][k][tx * 4];
            acc[0][0] = ffma2(a2.x, b2.x, acc[0][0]);
            acc[0][1] = ffma2(a2.x, b2.y, acc[0][1]);
            acc[1][0] = ffma2(a2.y, b2.x, acc[1][0]);
            acc[1][1] = ffma2(a2.y, b2.y, acc[1][1]);
        }
        if (t < 15) {
            s.As2[nxt][lk4+0][lm] = splat2(a_reg.x); s.As2[nxt][lk4+1][lm] = splat2(a_reg.y);
            s.As2[nxt][lk4+2][lm] = splat2(a_reg.z); s.As2[nxt][lk4+3][lm] = splat2(a_reg.w);
            *(float4*)&s.Bs[nxt][bk][bn4] = b_reg;
        }
        __syncthreads();
    }

    #pragma unroll
    for (int i = 0; i < 2; i++) {
        long r = mBase + ty * 2 + i;
        long off = r * 512 + nBase + tx * 4;
        float2 lo = u2f(acc[i][0]), hi = u2f(acc[i][1]);
        float4 v;
        v.x = alpha * lo.x; v.y = alpha * lo.y;
        v.z = alpha * hi.x; v.w = alpha * hi.y;
        if (Y) {
            float4 y = *(const float4*)&Y[off];
            v.x += beta * y.x; v.y += beta * y.y; v.z += beta * y.z; v.w += beta * y.w;
        }
        *(float4*)&O[off] = v;
    }
}

// ============ small GEMM core: [4096x64] rows-tile(64) vs W, ntiles K-tiles of 32 ============
// tile i: A = Aps[i>>1], k offset (i&1)*32; W row = (i>>1)*64 + (i&1)*32
__device__ __forceinline__ void mm64_core(
        SmemG& s, const float* A0, const float* A1,
        const float* A2, const float* W,
        int ntiles, int mBase, u64 (&acc)[2][2]) {
    int tid = threadIdx.x;
    int tx = tid & 15, ty = tid >> 4;
    int lm  = tid >> 3;
    int lk4 = (tid & 7) << 2;
    int bk  = tid >> 4;
    int bn4 = (tid & 15) << 2;

    const float* Aps[3] = {A0, A1, A2};
    float4 a_reg, b_reg;

    a_reg = *(const float4*)&A0[(long)(mBase + lm) * 64 + lk4];
    b_reg = *(const float4*)&W[(long)bk * 64 + bn4];
    s.As2[0][lk4+0][lm] = splat2(a_reg.x); s.As2[0][lk4+1][lm] = splat2(a_reg.y);
    s.As2[0][lk4+2][lm] = splat2(a_reg.z); s.As2[0][lk4+3][lm] = splat2(a_reg.w);
    *(float4*)&s.Bs[0][bk][bn4] = b_reg;
    __syncthreads();

    for (int tile = 0; tile < ntiles; tile++) {
        int cur = tile & 1, nxt = cur ^ 1;
        if (tile + 1 < ntiles) {
            int p  = (tile + 1) >> 1;
            int kk = ((tile + 1) & 1) * 32;
            const float* A = Aps[p];
            int wr = p * 64 + kk;
            a_reg = *(const float4*)&A[(long)(mBase + lm) * 64 + kk + lk4];
            b_reg = *(const float4*)&W[(long)(wr + bk) * 64 + bn4];
        }
        #pragma unroll
        for (int k = 0; k < 32; k++) {
            ulonglong2 a2 = *(const ulonglong2*)&s.As2[cur][k][ty * 2];
            ulonglong2 b2 = *(const ulonglong2*)&s.Bs[cur][k][tx * 4];
            acc[0][0] = ffma2(a2.x, b2.x, acc[0][0]);
            acc[0][1] = ffma2(a2.x, b2.y, acc[0][1]);
            acc[1][0] = ffma2(a2.y, b2.x, acc[1][0]);
            acc[1][1] = ffma2(a2.y, b2.y, acc[1][1]);
        }
        if (tile + 1 < ntiles) {
            s.As2[nxt][lk4+0][lm] = splat2(a_reg.x); s.As2[nxt][lk4+1][lm] = splat2(a_reg.y);
            s.As2[nxt][lk4+2][lm] = splat2(a_reg.z); s.As2[nxt][lk4+3][lm] = splat2(a_reg.w);
            *(float4*)&s.Bs[nxt][bk][bn4] = b_reg;
        }
        __syncthreads();
    }
}

// gate epilogue over a 64-row tile. g==0: z=sigmoid; g==1: hr=h*sigmoid; g==2: h=z*h+(1-z)*tanh
__device__ __forceinline__ void gate_epilogue(u64 (&acc)[2][2], int g, int mBase,
                                              const float* Xc) {
    int tid = threadIdx.x;
    int tx = tid & 15, ty = tid >> 4;
    int c = tx * 4;
    #pragma unroll
    for (int i = 0; i < 2; i++) {
        long r = mBase + ty * 2 + i;
        long off = r * 64 + c;
        float4 xc = *(const float4*)&Xc[off];
        float2 lo = u2f(acc[i][0]), hi = u2f(acc[i][1]);
        float v0 = lo.x + xc.x, v1 = lo.y + xc.y;
        float v2 = hi.x + xc.z, v3 = hi.y + xc.w;
        if (g == 0) {
            float4 o;
            o.x = 1.0f / (1.0f + expf(-v0)); o.y = 1.0f / (1.0f + expf(-v1));
            o.z = 1.0f / (1.0f + expf(-v2)); o.w = 1.0f / (1.0f + expf(-v3));
            *(float4*)&g_z[off] = o;
        } else if (g == 1) {
            float4 hv = *(const float4*)&g_h[off];
            float4 o;
            o.x = hv.x / (1.0f + expf(-v0)); o.y = hv.y / (1.0f + expf(-v1));
            o.z = hv.z / (1.0f + expf(-v2)); o.w = hv.w / (1.0f + expf(-v3));
            *(float4*)&g_hr[off] = o;
        } else {
            float4 hv = *(const float4*)&g_h[off];
            float4 zv = *(const float4*)&g_z[off];
            float4 o;
            o.x = zv.x * hv.x + (1.0f - zv.x) * tanhf(v0);
            o.y = zv.y * hv.y + (1.0f - zv.y) * tanhf(v1);
            o.z = zv.z * hv.z + (1.0f - zv.z) * tanhf(v2);
            o.w = zv.w * hv.w + (1.0f - zv.w) * tanhf(v3);
            *(float4*)&g_h[off] = o;
        }
    }
}

// predict one 64(s) x 32(t) tile for batch b, 512 threads, 4 outputs each
__device__ __forceinline__ void predict_tile(
        SmemP& s, int b, int sBase, int tBase,
        const float* b1, const float* W2,
        const float* b2, float* out) {
    int tid = threadIdx.x;
    __syncthreads();
    #pragma unroll
    for (int i = tid; i < 4096; i += NTHREADS) {
        int r = i >> 6, cc = i & 63;
        s.sps[r][cc] = g_sp[((long)(sBase + r) * Bb + b) * Hh + cc] + b1[cc];
    }
    #pragma unroll
    for (int i = tid; i < 2048; i += NTHREADS) {
        int r = i >> 6, cc = i & 63;
        s.tps[r][cc] = g_tp[((long)(tBase + r) * Bb + b) * Hh + cc];
    }
    if (tid < 64) s.w2[tid] = W2[tid];
    __syncthreads();

    int tx = tid & 31, ty = tid >> 5;   // ty 0..15
    float bias = b2[0];
    float a0 = bias, a1 = bias, a2 = bias, a3 = bias;
    #pragma unroll
    for (int hh = 0; hh < 64; hh++) {
        float tv = s.tps[tx][hh];
        float w  = s.w2[hh];
        a0 += fmaxf(s.sps[ty +  0][hh] + tv, 0.0f) * w;
        a1 += fmaxf(s.sps[ty + 16][hh] + tv, 0.0f) * w;
        a2 += fmaxf(s.sps[ty + 32][hh] + tv, 0.0f) * w;
        a3 += fmaxf(s.sps[ty + 48][hh] + tv, 0.0f) * w;
    }
    long colBase = (long)b * Nn * Nn + (long)tBase + tx;
    out[colBase + (long)(sBase + ty +  0) * Nn] = a0;
    out[colBase + (long)(sBase + ty + 16) * Nn] = a1;
    out[colBase + (long)(sBase + ty + 32) * Nn] = a2;
    out[colBase + (long)(sBase + ty + 48) * Nn] = a3;
}

// ============ THE ONLY KERNEL: 128 CTAs x 512 threads, persistent ============
__global__ __launch_bounds__(NTHREADS, 1) void mega_kernel(
        const float* x, const float* ew,
        const float* Wx, const float* bx,
        const float* Wh, const float* bh,
        const float* W1, const float* b1,
        const float* W2, const float* b2,
        const void*  ei,
        float* out) {
    extern __shared__ __align__(16) char smraw[];
    SmemG& sg = *(SmemG*)smraw;
    SmemP& smp = *(SmemP*)smraw;

    const int c = blockIdx.x;
    const int tid = threadIdx.x;
    const long gtid = (long)c * NTHREADS + tid;   // 0..65535
    unsigned bph = 0;
    if (tid == 0) bph = ld_acq(&g_barPhase);

    // ---- Phase 0: probe + zero + graph build ----
    if (c == 0 && tid == 0) {
        const long long* p = (const long long*)ei;
        int is64 = 1;
        for (int i = 0; i < 64; i++) {
            long long v = p[i];
            if (v < 0 || v >= (long long)Nn) { is64 = 0; break; }
        }
        g_idx32 = is64 ? 0 : 1;
    }
    {
        float4 zz = make_float4(0.f, 0.f, 0.f, 0.f);
        *(float4*)&g_S[gtid * 4] = zz;
        *(float4*)&g_h[gtid * 4] = zz;
        if (gtid < Nn) g_deg[gtid] = 0.0f;
    }
    grid_bar(bph);
    if (gtid < Ee) atomicAdd(&g_deg[load_idx(ei, gtid)], ew[gtid]);
    grid_bar(bph);
    if (gtid < Nn) {
        float d = g_deg[gtid];
        g_dinv[gtid] = (d > 0.0f) ? rsqrtf(fmaxf(d, 1e-12f)) : 0.0f;
    }
    grid_bar(bph);
    if (gtid < Ee) {
        int s = load_idx(ei, gtid);
        int d = load_idx(ei, (long)Ee + gtid);
        atomicAdd(&g_S[(long)d * Nn + s], -ew[gtid] * g_dinv[s] * g_dinv[d]);
    }
    grid_bar(bph);

    // ---- Phase A: S2 = S @ S (CTAs 0..63) | permute x -> U0 (CTAs 64..127) ----
    // TOTAL x elements = B*T*N*C = 4,194,304 -> 65536 per permute CTA (64 CTAs).
    // (R9/R10 bug was 32768 here: only half of x permuted.)
    if (c < 64) {
        gemm512_core(sg, g_S, g_S, (const float*)0, g_S2, 1.0f, 0.0f,
                     (c >> 3) * 64, (c & 7) * 64);
    } else {
        long base = (long)(c - 64) * 65536;
        for (long i = base + tid; i < base + 65536; i += NTHREADS) {
            int cc = (int)(i & 63);
            long r = i >> 6;
            int n = (int)(r % Nn); r /= Nn;
            int t = (int)(r % Tt);
            int b = (int)(r / Tt);
            g_U[((long)(t*3) * NB + (long)n * Bb + b) * Hh + cc] = x[i];
        }
    }
    grid_bar(bph);

    // ---- Phase B: x-basis. 16t x {U1,U2} x 64 tiles = 2048 units, 16/CTA ----
    for (int i = 0; i < 16; i++) {
        int unit = c + NCTAS * i;
        int t = unit >> 7, w = (unit >> 6) & 1, tile = unit & 63;
        int mB = (tile >> 3) * 64, nB = (tile & 7) * 64;
        const float* U0 = g_U + (long)(t*3) * MAT;
        if (w == 0)
            gemm512_core(sg, g_S,  U0, (const float*)0, g_U + (long)(t*3+1)*MAT, 1.0f,  0.0f, mB, nB);
        else
            gemm512_core(sg, g_S2, U0, U0,              g_U + (long)(t*3+2)*MAT, 2.0f, -1.0f, mB, nB);
    }
    grid_bar(bph);

    // ---- Phase C: Xc[t][lg] = sum_k U[t][k] @ Wx[lg][k] + bx + bh.  16x6x64 units, 48/CTA ----
    for (int i = 0; i < 48; i++) {
        int unit = c + NCTAS * i;
        int t = unit / 384;
        int rem = unit % 384;
        int lg = rem >> 6;
        int mB = (rem & 63) * 64;
        const float* A0 = g_U + (long)(t*3 + 0) * MAT;
        const float* A1 = g_U + (long)(t*3 + 1) * MAT;
        const float* A2 = g_U + (long)(t*3 + 2) * MAT;
        u64 acc[2][2] = {{0ull,0ull},{0ull,0ull}};
        mm64_core(sg, A0, A1, A2, Wx + (long)lg * 3 * (Cc*Hh), 6, mB, acc);
        int tx = tid & 15, ty = tid >> 4;
        int cc = tx * 4;
        float* o = g_Xc + ((long)(t*Ll + lg/3) * 3 + (lg % 3)) * MAT;
        float b0 = bx[lg*Hh + cc+0] + bh[lg*Hh + cc+0];
        float b1v = bx[lg*Hh + cc+1] + bh[lg*Hh + cc+1];
        float b2v = bx[lg*Hh + cc+2] + bh[lg*Hh + cc+2];
        float b3 = bx[lg*Hh + cc+3] + bh[lg*Hh + cc+3];
        #pragma unroll
        for (int j = 0; j < 2; j++) {
            long r = mB + ty * 2 + j;
            float2 lo = u2f(acc[j][0]), hi = u2f(acc[j][1]);
            float4 v;
            v.x = lo.x + b0; v.y = lo.y + b1v; v.z = hi.x + b2v; v.w = hi.y + b3;
            *(float4*)&o[r * 64 + cc] = v;
        }
    }
    grid_bar(bph);

    // ---- Phase D: recurrent chain, 32 cells x 4 stages ----
    for (int cell = 0; cell < Tt * Ll; cell++) {
        int t = cell >> 1, l = cell & 1;
        const float* Wl    = Wh + (long)l * 9 * (Hh*Hh);
        const float* Xc_tl = g_Xc + ((long)(t*Ll + l) * 3) * MAT;
        int tile = c & 63;
        int mB512 = (tile >> 3) * 64, nB512 = (tile & 7) * 64;

        // stage 1: T1 = S h (c<64) | T2 = 2 S2 h - h (c>=64)
        if (c < 64) gemm512_core(sg, g_S,  g_h, (const float*)0, g_T1, 1.0f,  0.0f, mB512, nB512);
        else        gemm512_core(sg, g_S2, g_h, g_h,             g_T2, 2.0f, -1.0f, mB512, nB512);
        grid_bar(bph);

        // stage 2: gates z (c<64) / r->hr (c>=64)
        {
            int g = c >> 6;
            u64 acc[2][2] = {{0ull,0ull},{0ull,0ull}};
            mm64_core(sg, g_h, g_T1, g_T2, Wl + (long)g * 3 * (Hh*Hh), 6, tile * 64, acc);
            gate_epilogue(acc, g, tile * 64, Xc_tl + (long)g * MAT);
        }
        grid_bar(bph);

        // stage 3: T1 = S hr | T2 = 2 S2 hr - hr
        if (c < 64) gemm512_core(sg, g_S,  g_hr, (const float*)0, g_T1, 1.0f,  0.0f, mB512, nB512);
        else        gemm512_core(sg, g_S2, g_hr, g_hr,            g_T2, 2.0f, -1.0f, mB512, nB512);
        grid_bar(bph);

        // stage 4: h~ gate + GRU update (CTAs 0..63)
        if (c < 64) {
            u64 acc[2][2] = {{0ull,0ull},{0ull,0ull}};
            mm64_core(sg, g_hr, g_T1, g_T2, Wl + (long)2 * 3 * (Hh*Hh), 6, c * 64, acc);
            gate_epilogue(acc, 2, c * 64, Xc_tl + (long)2 * MAT);
        }
        grid_bar(bph);
    }

    // ---- Phase E: sp/tp projections ----
    {
        int half = c >> 6;
        int mB = (c & 63) * 64;
        u64 acc[2][2] = {{0ull,0ull},{0ull,0ull}};
        mm64_core(sg, g_h, g_h, g_h, W1 + (long)half * (Hh*Hh), 2, mB, acc);
        int tx = tid & 15, ty = tid >> 4;
        float* o = half ? g_tp : g_sp;
        #pragma unroll
        for (int j = 0; j < 2; j++) {
            long r = mB + ty * 2 + j;
            float2 lo = u2f(acc[j][0]), hi = u2f(acc[j][1]);
            float4 v; v.x = lo.x; v.y = lo.y; v.z = hi.x; v.w = hi.y;
            *(float4*)&o[r * 64 + tx * 4] = v;
        }
    }
    grid_bar(bph);

    // ---- Phase F: all-pairs logits. 8b x 8sT x 16tT = 1024 tiles (64x32), 8/CTA ----
    for (int i = 0; i < 8; i++) {
        int unit = c * 8 + i;
        int b  = unit & 7;
        int sT = (unit >> 3) & 7;
        int tT = (unit >> 6) & 15;
        predict_tile(smp, b, sT * 64, tT * 32, b1, W2, b2, out);
    }
}

// ---------------- host: ONE launch ----------------
extern "C" void kernel_launch(void* const* d_in, const int* in_sizes, int n_in,
                              void* d_out, int out_size) {
    const float* x   = (const float*)d_in[0];
    const float* ew  = (const float*)d_in[1];
    const float* Wx  = (const float*)d_in[2];
    const float* bx  = (const float*)d_in[3];
    const float* Wh  = (const float*)d_in[4];
    const float* bh  = (const float*)d_in[5];
    const float* W1  = (const float*)d_in[6];
    const float* b1  = (const float*)d_in[7];
    const float* W2  = (const float*)d_in[8];
    const float* b2  = (const float*)d_in[9];
    const void*  ei  = d_in[10];
    float* out = (float*)d_out;

    cudaFuncSetAttribute(mega_kernel,
                         cudaFuncAttributeMaxDynamicSharedMemorySize,
                         (int)SMEM_BYTES);
    mega_kernel<<<NCTAS, NTHREADS, SMEM_BYTES>>>(x, ew, Wx, bx, Wh, bh,
                                                 W1, b1, W2, b2, ei, out);
}

// round 12
// speedup vs baseline: 1.6494x; 1.6494x over previous
#include <cuda_runtime.h>
#include <math.h>

#define Nn 512
#define Bb 8
#define Cc 64
#define Hh 64
#define Tt 16
#define Ll 2
#define Ee 16384
#define NB (Nn*Bb)          /* 4096 rows for gate GEMMs */
#define MAT (NB*Hh)         /* 262144 floats per [N,B,H] matrix */
#define NCTAS 128
#define NTHREADS 512

typedef unsigned long long u64;

// ---------------- device scratch ----------------
__device__ float g_deg[Nn];
__device__ float g_dinv[Nn];
__device__ int   g_cnt[Nn];
__device__ int   g_fill[Nn];
__device__ int   g_rowptr[Nn + 1];
__device__ int   g_col[Ee];
__device__ float g_val[Ee];
__device__ float g_U[(long)Tt*3*MAT];
__device__ float g_Xc[(long)Tt*Ll*3*MAT];
__device__ float g_h[MAT];
__device__ float g_z[MAT];
__device__ float g_hr[MAT];
__device__ float g_T1[MAT];
__device__ float g_T2[MAT];
__device__ float g_sp[MAT];
__device__ float g_tp[MAT];
__device__ int   g_idx32;
__device__ unsigned g_barCount = 0;   // returns to 0 after each barrier
__device__ unsigned g_barPhase = 0;   // monotonic across launches (wrap-safe)

// ---------------- f32x2 helpers ----------------
__device__ __forceinline__ u64 ffma2(u64 a, u64 b, u64 c) {
    u64 d;
    asm("fma.rn.f32x2 %0, %1, %2, %3;" : "=l"(d) : "l"(a), "l"(b), "l"(c));
    return d;
}
__device__ __forceinline__ u64 splat2(float x) {
    u64 r;
    asm("mov.b64 %0, {%1, %1};" : "=l"(r) : "r"(__float_as_uint(x)));
    return r;
}
__device__ __forceinline__ float2 u2f(u64 v) {
    float2 f;
    asm("mov.b64 {%0, %1}, %2;" : "=f"(f.x), "=f"(f.y) : "l"(v));
    return f;
}

// ---------------- grid barrier (persistent kernel, replay-proof) ----------------
__device__ __forceinline__ unsigned ld_acq(unsigned* p) {
    unsigned v;
    asm volatile("ld.acquire.gpu.u32 %0, [%1];" : "=r"(v) : "l"(p) : "memory");
    return v;
}
__device__ __forceinline__ void st_rel(unsigned* p, unsigned v) {
    asm volatile("st.release.gpu.u32 [%0], %1;" :: "l"(p), "r"(v) : "memory");
}
__device__ __forceinline__ unsigned atom_add_acqrel(unsigned* p, unsigned v) {
    unsigned old;
    asm volatile("atom.acq_rel.gpu.add.u32 %0, [%1], %2;" : "=r"(old) : "l"(p), "r"(v) : "memory");
    return old;
}
__device__ __forceinline__ void grid_bar(unsigned& bph) {
    __syncthreads();
    bph += 1;
    if (threadIdx.x == 0) {
        unsigned old = atom_add_acqrel(&g_barCount, 1u);
        if (old == NCTAS - 1) {
            g_barCount = 0;
            st_rel(&g_barPhase, bph);
        } else {
            while ((int)(ld_acq(&g_barPhase) - bph) < 0) { __nanosleep(32); }
        }
    }
    __syncthreads();
}

// ---------------- shared memory ----------------
struct SmemG {
    __align__(16) u64   As2[2][32][66];
    __align__(16) float Bs[2][32][64];
};
struct SmemP {
    float sps[64][65];
    float tps[32][65];
    float w2[64];
};
#define SMEM_BYTES (sizeof(SmemG) > sizeof(SmemP) ? sizeof(SmemG) : sizeof(SmemP))

__device__ __forceinline__ int load_idx(const void* ei, long i) {
    if (g_idx32) return ((const int*)ei)[i];
    return (int)(((const long long*)ei)[i]);
}

// ============ SPARSE S-apply: dst[n][c] = alpha * sum_nnz w * X[k][c] (+ beta*Y) ============
// One warp handles one (node, 128-col block): 2048 warp-units == 2048 warps chipwide.
__device__ __forceinline__ void sparse_apply(
        float* dst, const float* X, const float* Y, float alpha, float beta) {
    int gw   = blockIdx.x * (NTHREADS / 32) + (threadIdx.x >> 5);  // 0..2047
    int lane = threadIdx.x & 31;
    int node = gw >> 2;
    int c0   = ((gw & 3) << 7) + lane * 4;
    int rp0 = g_rowptr[node], rp1 = g_rowptr[node + 1];

    float ax = 0.f, ay = 0.f, az = 0.f, aw = 0.f;
    int i = rp0;
    for (; i + 4 <= rp1; i += 4) {
        int   k0 = g_col[i],   k1 = g_col[i+1], k2 = g_col[i+2], k3 = g_col[i+3];
        float w0 = g_val[i],   w1 = g_val[i+1], w2 = g_val[i+2], w3 = g_val[i+3];
        float4 x0 = *(const float4*)&X[(long)k0 * 512 + c0];
        float4 x1 = *(const float4*)&X[(long)k1 * 512 + c0];
        float4 x2 = *(const float4*)&X[(long)k2 * 512 + c0];
        float4 x3 = *(const float4*)&X[(long)k3 * 512 + c0];
        ax = fmaf(w0, x0.x, ax); ay = fmaf(w0, x0.y, ay); az = fmaf(w0, x0.z, az); aw = fmaf(w0, x0.w, aw);
        ax = fmaf(w1, x1.x, ax); ay = fmaf(w1, x1.y, ay); az = fmaf(w1, x1.z, az); aw = fmaf(w1, x1.w, aw);
        ax = fmaf(w2, x2.x, ax); ay = fmaf(w2, x2.y, ay); az = fmaf(w2, x2.z, az); aw = fmaf(w2, x2.w, aw);
        ax = fmaf(w3, x3.x, ax); ay = fmaf(w3, x3.y, ay); az = fmaf(w3, x3.z, az); aw = fmaf(w3, x3.w, aw);
    }
    for (; i < rp1; i++) {
        int k = g_col[i]; float w = g_val[i];
        float4 xv = *(const float4*)&X[(long)k * 512 + c0];
        ax = fmaf(w, xv.x, ax); ay = fmaf(w, xv.y, ay);
        az = fmaf(w, xv.z, az); aw = fmaf(w, xv.w, aw);
    }
    long off = (long)node * 512 + c0;
    float4 o;
    o.x = alpha * ax; o.y = alpha * ay; o.z = alpha * az; o.w = alpha * aw;
    if (Y) {
        float4 y = *(const float4*)&Y[off];
        o.x += beta * y.x; o.y += beta * y.y; o.z += beta * y.z; o.w += beta * y.w;
    }
    *(float4*)&dst[off] = o;
}

// ============ small GEMM core: [4096x64] rows-tile(64) vs W, ntiles K-tiles of 32 ============
__device__ __forceinline__ void mm64_core(
        SmemG& s, const float* A0, const float* A1,
        const float* A2, const float* W,
        int ntiles, int mBase, u64 (&acc)[2][2]) {
    int tid = threadIdx.x;
    int tx = tid & 15, ty = tid >> 4;
    int lm  = tid >> 3;
    int lk4 = (tid & 7) << 2;
    int bk  = tid >> 4;
    int bn4 = (tid & 15) << 2;

    const float* Aps[3] = {A0, A1, A2};
    float4 a_reg, b_reg;

    a_reg = *(const float4*)&A0[(long)(mBase + lm) * 64 + lk4];
    b_reg = *(const float4*)&W[(long)bk * 64 + bn4];
    s.As2[0][lk4+0][lm] = splat2(a_reg.x); s.As2[0][lk4+1][lm] = splat2(a_reg.y);
    s.As2[0][lk4+2][lm] = splat2(a_reg.z); s.As2[0][lk4+3][lm] = splat2(a_reg.w);
    *(float4*)&s.Bs[0][bk][bn4] = b_reg;
    __syncthreads();

    for (int tile = 0; tile < ntiles; tile++) {
        int cur = tile & 1, nxt = cur ^ 1;
        if (tile + 1 < ntiles) {
            int p  = (tile + 1) >> 1;
            int kk = ((tile + 1) & 1) * 32;
            const float* A = Aps[p];
            int wr = p * 64 + kk;
            a_reg = *(const float4*)&A[(long)(mBase + lm) * 64 + kk + lk4];
            b_reg = *(const float4*)&W[(long)(wr + bk) * 64 + bn4];
        }
        #pragma unroll
        for (int k = 0; k < 32; k++) {
            ulonglong2 a2 = *(const ulonglong2*)&s.As2[cur][k][ty * 2];
            ulonglong2 b2 = *(const ulonglong2*)&s.Bs[cur][k][tx * 4];
            acc[0][0] = ffma2(a2.x, b2.x, acc[0][0]);
            acc[0][1] = ffma2(a2.x, b2.y, acc[0][1]);
            acc[1][0] = ffma2(a2.y, b2.x, acc[1][0]);
            acc[1][1] = ffma2(a2.y, b2.y, acc[1][1]);
        }
        if (tile + 1 < ntiles) {
            s.As2[nxt][lk4+0][lm] = splat2(a_reg.x); s.As2[nxt][lk4+1][lm] = splat2(a_reg.y);
            s.As2[nxt][lk4+2][lm] = splat2(a_reg.z); s.As2[nxt][lk4+3][lm] = splat2(a_reg.w);
            *(float4*)&s.Bs[nxt][bk][bn4] = b_reg;
        }
        __syncthreads();
    }
}

// gate epilogue: g==0: z=sigmoid; g==1: hr=h*sigmoid; g==2: h=z*h+(1-z)*tanh
__device__ __forceinline__ void gate_epilogue(u64 (&acc)[2][2], int g, int mBase,
                                              const float* Xc) {
    int tid = threadIdx.x;
    int tx = tid & 15, ty = tid >> 4;
    int c = tx * 4;
    #pragma unroll
    for (int i = 0; i < 2; i++) {
        long r = mBase + ty * 2 + i;
        long off = r * 64 + c;
        float4 xc = *(const float4*)&Xc[off];
        float2 lo = u2f(acc[i][0]), hi = u2f(acc[i][1]);
        float v0 = lo.x + xc.x, v1 = lo.y + xc.y;
        float v2 = hi.x + xc.z, v3 = hi.y + xc.w;
        if (g == 0) {
            float4 o;
            o.x = 1.0f / (1.0f + expf(-v0)); o.y = 1.0f / (1.0f + expf(-v1));
            o.z = 1.0f / (1.0f + expf(-v2)); o.w = 1.0f / (1.0f + expf(-v3));
            *(float4*)&g_z[off] = o;
        } else if (g == 1) {
            float4 hv = *(const float4*)&g_h[off];
            float4 o;
            o.x = hv.x / (1.0f + expf(-v0)); o.y = hv.y / (1.0f + expf(-v1));
            o.z = hv.z / (1.0f + expf(-v2)); o.w = hv.w / (1.0f + expf(-v3));
            *(float4*)&g_hr[off] = o;
        } else {
            float4 hv = *(const float4*)&g_h[off];
            float4 zv = *(const float4*)&g_z[off];
            float4 o;
            o.x = zv.x * hv.x + (1.0f - zv.x) * tanhf(v0);
            o.y = zv.y * hv.y + (1.0f - zv.y) * tanhf(v1);
            o.z = zv.z * hv.z + (1.0f - zv.z) * tanhf(v2);
            o.w = zv.w * hv.w + (1.0f - zv.w) * tanhf(v3);
            *(float4*)&g_h[off] = o;
        }
    }
}

// predict one 64(s) x 32(t) tile for batch b, 512 threads, 4 outputs each
__device__ __forceinline__ void predict_tile(
        SmemP& s, int b, int sBase, int tBase,
        const float* b1, const float* W2,
        const float* b2, float* out) {
    int tid = threadIdx.x;
    __syncthreads();
    #pragma unroll
    for (int i = tid; i < 4096; i += NTHREADS) {
        int r = i >> 6, cc = i & 63;
        s.sps[r][cc] = g_sp[((long)(sBase + r) * Bb + b) * Hh + cc] + b1[cc];
    }
    #pragma unroll
    for (int i = tid; i < 2048; i += NTHREADS) {
        int r = i >> 6, cc = i & 63;
        s.tps[r][cc] = g_tp[((long)(tBase + r) * Bb + b) * Hh + cc];
    }
    if (tid < 64) s.w2[tid] = W2[tid];
    __syncthreads();

    int tx = tid & 31, ty = tid >> 5;
    float bias = b2[0];
    float a0 = bias, a1 = bias, a2 = bias, a3 = bias;
    #pragma unroll
    for (int hh = 0; hh < 64; hh++) {
        float tv = s.tps[tx][hh];
        float w  = s.w2[hh];
        a0 += fmaxf(s.sps[ty +  0][hh] + tv, 0.0f) * w;
        a1 += fmaxf(s.sps[ty + 16][hh] + tv, 0.0f) * w;
        a2 += fmaxf(s.sps[ty + 32][hh] + tv, 0.0f) * w;
        a3 += fmaxf(s.sps[ty + 48][hh] + tv, 0.0f) * w;
    }
    long colBase = (long)b * Nn * Nn + (long)tBase + tx;
    out[colBase + (long)(sBase + ty +  0) * Nn] = a0;
    out[colBase + (long)(sBase + ty + 16) * Nn] = a1;
    out[colBase + (long)(sBase + ty + 32) * Nn] = a2;
    out[colBase + (long)(sBase + ty + 48) * Nn] = a3;
}

// ============ THE ONLY KERNEL: 128 CTAs x 512 threads, persistent ============
__global__ __launch_bounds__(NTHREADS, 1) void mega_kernel(
        const float* x, const float* ew,
        const float* Wx, const float* bx,
        const float* Wh, const float* bh,
        const float* W1, const float* b1,
        const float* W2, const float* b2,
        const void*  ei,
        float* out) {
    extern __shared__ __align__(16) char smraw[];
    SmemG& sg = *(SmemG*)smraw;
    SmemP& smp = *(SmemP*)smraw;

    const int c = blockIdx.x;
    const int tid = threadIdx.x;
    const long gtid = (long)c * NTHREADS + tid;   // 0..65535
    unsigned bph = 0;
    if (tid == 0) bph = ld_acq(&g_barPhase);

    // ---- Phase 0a: probe + zero ----
    if (c == 0 && tid == 0) {
        const long long* p = (const long long*)ei;
        int is64 = 1;
        for (int i = 0; i < 64; i++) {
            long long v = p[i];
            if (v < 0 || v >= (long long)Nn) { is64 = 0; break; }
        }
        g_idx32 = is64 ? 0 : 1;
    }
    {
        float4 zz = make_float4(0.f, 0.f, 0.f, 0.f);
        *(float4*)&g_h[gtid * 4] = zz;
        if (gtid < Nn) { g_deg[gtid] = 0.0f; g_cnt[gtid] = 0; g_fill[gtid] = 0; }
    }
    grid_bar(bph);

    // ---- Phase 0b: degree + per-dst counts ----
    if (gtid < Ee) {
        int s = load_idx(ei, gtid);
        int d = load_idx(ei, (long)Ee + gtid);
        atomicAdd(&g_deg[s], ew[gtid]);
        atomicAdd(&g_cnt[d], 1);
    }
    grid_bar(bph);

    // ---- Phase 0c: dinv + CSR rowptr scan ----
    if (gtid < Nn) {
        float d = g_deg[gtid];
        g_dinv[gtid] = (d > 0.0f) ? rsqrtf(fmaxf(d, 1e-12f)) : 0.0f;
    }
    if (c == 0 && tid == 0) {
        int acc = 0;
        for (int i = 0; i < Nn; i++) { g_rowptr[i] = acc; acc += g_cnt[i]; }
        g_rowptr[Nn] = acc;
    }
    grid_bar(bph);

    // ---- Phase 0d: CSR fill ----
    if (gtid < Ee) {
        int s = load_idx(ei, gtid);
        int d = load_idx(ei, (long)Ee + gtid);
        int slot = atomicAdd(&g_fill[d], 1);
        int idx = g_rowptr[d] + slot;
        g_col[idx] = s;
        g_val[idx] = -ew[gtid] * g_dinv[s] * g_dinv[d];
    }
    grid_bar(bph);

    // ---- Phase A: permute x -> U0, all CTAs (4,194,304 elements / 128 = 32768) ----
    {
        long base = (long)c * 32768;
        for (long i = base + tid; i < base + 32768; i += NTHREADS) {
            int cc = (int)(i & 63);
            long r = i >> 6;
            int n = (int)(r % Nn); r /= Nn;
            int t = (int)(r % Tt);
            int b = (int)(r / Tt);
            g_U[((long)(t*3) * NB + (long)n * Bb + b) * Hh + cc] = x[i];
        }
    }
    grid_bar(bph);

    // ---- Phase B: x-basis via sparse S. B1: U1[t] = S@U0[t] for all t ----
    for (int t = 0; t < Tt; t++) {
        const float* U0 = g_U + (long)(t*3) * MAT;
        sparse_apply(g_U + (long)(t*3+1)*MAT, U0, (const float*)0, 1.0f, 0.0f);
    }
    grid_bar(bph);
    // B2: U2[t] = 2 S@U1[t] - U0[t]
    for (int t = 0; t < Tt; t++) {
        const float* U0 = g_U + (long)(t*3) * MAT;
        const float* U1 = g_U + (long)(t*3+1) * MAT;
        sparse_apply(g_U + (long)(t*3+2)*MAT, U1, U0, 2.0f, -1.0f);
    }
    grid_bar(bph);

    // ---- Phase C: Xc[t][lg] = sum_k U[t][k] @ Wx[lg][k] + bx + bh.  16x6x64 units, 48/CTA ----
    for (int i = 0; i < 48; i++) {
        int unit = c + NCTAS * i;
        int t = unit / 384;
        int rem = unit % 384;
        int lg = rem >> 6;
        int mB = (rem & 63) * 64;
        const float* A0 = g_U + (long)(t*3 + 0) * MAT;
        const float* A1 = g_U + (long)(t*3 + 1) * MAT;
        const float* A2 = g_U + (long)(t*3 + 2) * MAT;
        u64 acc[2][2] = {{0ull,0ull},{0ull,0ull}};
        mm64_core(sg, A0, A1, A2, Wx + (long)lg * 3 * (Cc*Hh), 6, mB, acc);
        int tx = tid & 15, ty = tid >> 4;
        int cc = tx * 4;
        float* o = g_Xc + ((long)(t*Ll + lg/3) * 3 + (lg % 3)) * MAT;
        float b0 = bx[lg*Hh + cc+0] + bh[lg*Hh + cc+0];
        float b1v = bx[lg*Hh + cc+1] + bh[lg*Hh + cc+1];
        float b2v = bx[lg*Hh + cc+2] + bh[lg*Hh + cc+2];
        float b3 = bx[lg*Hh + cc+3] + bh[lg*Hh + cc+3];
        #pragma unroll
        for (int j = 0; j < 2; j++) {
            long r = mB + ty * 2 + j;
            float2 lo = u2f(acc[j][0]), hi = u2f(acc[j][1]);
            float4 v;
            v.x = lo.x + b0; v.y = lo.y + b1v; v.z = hi.x + b2v; v.w = hi.y + b3;
            *(float4*)&o[r * 64 + cc] = v;
        }
    }
    grid_bar(bph);

    // ---- Phase D: recurrent chain, 32 cells x 6 light stages ----
    for (int cell = 0; cell < Tt * Ll; cell++) {
        int t = cell >> 1, l = cell & 1;
        const float* Wl    = Wh + (long)l * 9 * (Hh*Hh);
        const float* Xc_tl = g_Xc + ((long)(t*Ll + l) * 3) * MAT;
        int tile = c & 63;

        // stage 1: T1 = S @ h  (sparse, all 2048 warps)
        sparse_apply(g_T1, g_h, (const float*)0, 1.0f, 0.0f);
        grid_bar(bph);
        // stage 2: T2 = 2 S @ T1 - h
        sparse_apply(g_T2, g_T1, g_h, 2.0f, -1.0f);
        grid_bar(bph);

        // stage 3: gates z (c<64) / r->hr (c>=64)
        {
            int g = c >> 6;
            u64 acc[2][2] = {{0ull,0ull},{0ull,0ull}};
            mm64_core(sg, g_h, g_T1, g_T2, Wl + (long)g * 3 * (Hh*Hh), 6, tile * 64, acc);
            gate_epilogue(acc, g, tile * 64, Xc_tl + (long)g * MAT);
        }
        grid_bar(bph);

        // stage 4: T1 = S @ hr
        sparse_apply(g_T1, g_hr, (const float*)0, 1.0f, 0.0f);
        grid_bar(bph);
        // stage 5: T2 = 2 S @ T1 - hr
        sparse_apply(g_T2, g_T1, g_hr, 2.0f, -1.0f);
        grid_bar(bph);

        // stage 6: h~ gate + GRU update (CTAs 0..63)
        if (c < 64) {
            u64 acc[2][2] = {{0ull,0ull},{0ull,0ull}};
            mm64_core(sg, g_hr, g_T1, g_T2, Wl + (long)2 * 3 * (Hh*Hh), 6, c * 64, acc);
            gate_epilogue(acc, 2, c * 64, Xc_tl + (long)2 * MAT);
        }
        grid_bar(bph);
    }

    // ---- Phase E: sp/tp projections ----
    {
        int half = c >> 6;
        int mB = (c & 63) * 64;
        u64 acc[2][2] = {{0ull,0ull},{0ull,0ull}};
        mm64_core(sg, g_h, g_h, g_h, W1 + (long)half * (Hh*Hh), 2, mB, acc);
        int tx = tid & 15, ty = tid >> 4;
        float* o = half ? g_tp : g_sp;
        #pragma unroll
        for (int j = 0; j < 2; j++) {
            long r = mB + ty * 2 + j;
            float2 lo = u2f(acc[j][0]), hi = u2f(acc[j][1]);
            float4 v; v.x = lo.x; v.y = lo.y; v.z = hi.x; v.w = hi.y;
            *(float4*)&o[r * 64 + tx * 4] = v;
        }
    }
    grid_bar(bph);

    // ---- Phase F: all-pairs logits. 8b x 8sT x 16tT = 1024 tiles (64x32), 8/CTA ----
    for (int i = 0; i < 8; i++) {
        int unit = c * 8 + i;
        int b  = unit & 7;
        int sT = (unit >> 3) & 7;
        int tT = (unit >> 6) & 15;
        predict_tile(smp, b, sT * 64, tT * 32, b1, W2, b2, out);
    }
}

// ---------------- host: ONE launch ----------------
extern "C" void kernel_launch(void* const* d_in, const int* in_sizes, int n_in,
                              void* d_out, int out_size) {
    const float* x   = (const float*)d_in[0];
    const float* ew  = (const float*)d_in[1];
    const float* Wx  = (const float*)d_in[2];
    const float* bx  = (const float*)d_in[3];
    const float* Wh  = (const float*)d_in[4];
    const float* bh  = (const float*)d_in[5];
    const float* W1  = (const float*)d_in[6];
    const float* b1  = (const float*)d_in[7];
    const float* W2  = (const float*)d_in[8];
    const float* b2  = (const float*)d_in[9];
    const void*  ei  = d_in[10];
    float* out = (float*)d_out;

    cudaFuncSetAttribute(mega_kernel,
                         cudaFuncAttributeMaxDynamicSharedMemorySize,
                         (int)SMEM_BYTES);
    mega_kernel<<<NCTAS, NTHREADS, SMEM_BYTES>>>(x, ew, Wx, bx, Wh, bh,
                                                 W1, b1, W2, b2, ei, out);
}